// round 11
// baseline (speedup 1.0000x reference)
#include <cuda_runtime.h>
#include <cuda_bf16.h>
#include <cstdint>

#define B_DIM 8192
#define S_DIM 256
#define R_DIM 8192
#define KSPLIT 4
#define KCHUNK (R_DIM / KSPLIT)             // 2048

// ---------------------------------------------------------------------------
// Device-global scratch
// ---------------------------------------------------------------------------
__device__ __nv_bfloat16 g_fhi[(size_t)B_DIM * R_DIM];  // 128 MB
__device__ __nv_bfloat16 g_flo[(size_t)B_DIM * R_DIM];  // 128 MB
__device__ __nv_bfloat16 g_ihi[(size_t)S_DIM * R_DIM];  // 4 MB
__device__ __nv_bfloat16 g_ilo[(size_t)S_DIM * R_DIM];  // 4 MB
__device__ float g_part[KSPLIT][(size_t)B_DIM * S_DIM]; // 32 MB partials
__device__ float g_logT[B_DIM];
__device__ float g_invT[B_DIM];
__device__ float g_expg[R_DIM];

// ---------------------------------------------------------------------------
// PTX helpers (compute_103-portable: mma.sync / ldmatrix / cp.async)
// ---------------------------------------------------------------------------
__device__ __forceinline__ uint32_t s2u(const void* p) {
    uint32_t a;
    asm("{ .reg .u64 t; cvta.to.shared.u64 t, %1; cvt.u32.u64 %0, t; }"
        : "=r"(a) : "l"(p));
    return a;
}

#define LDSM4(r, addr)                                                         \
    asm volatile("ldmatrix.sync.aligned.m8n8.x4.shared.b16 {%0,%1,%2,%3}, [%4];" \
                 : "=r"((r)[0]), "=r"((r)[1]), "=r"((r)[2]), "=r"((r)[3])      \
                 : "r"(addr))

#define MMA16816(c, a, b0, b1)                                                 \
    asm volatile("mma.sync.aligned.m16n8k16.row.col.f32.bf16.bf16.f32 "        \
                 "{%0,%1,%2,%3}, {%4,%5,%6,%7}, {%8,%9}, {%0,%1,%2,%3};"       \
                 : "+f"((c)[0]), "+f"((c)[1]), "+f"((c)[2]), "+f"((c)[3])      \
                 : "r"((a)[0]), "r"((a)[1]), "r"((a)[2]), "r"((a)[3]),         \
                   "r"(b0), "r"(b1))

#define CP16(saddr, gptr)                                                      \
    asm volatile("cp.async.cg.shared.global [%0], [%1], 16;"                   \
                 :: "r"(saddr), "l"(gptr))

#define CP_COMMIT() asm volatile("cp.async.commit_group;" ::: "memory")
#define CP_WAIT1()  asm volatile("cp.async.wait_group 1;" ::: "memory")

// ---------------------------------------------------------------------------
// Kernel 0: per-b and per-r precomputation
// ---------------------------------------------------------------------------
__global__ void precompute_kernel(const float* __restrict__ temperature,
                                  const float* __restrict__ gamma)
{
    int i = blockIdx.x * blockDim.x + threadIdx.x;
    if (i < B_DIM) {
        float T = temperature[i];
        g_logT[i] = logf(T * (1.0f / 300.0f));
        g_invT[i] = 1.0f / T;
    }
    if (i < R_DIM) {
        g_expg[i] = expf(-gamma[i]);
    }
}

// ---------------------------------------------------------------------------
// Kernel 0b: split incidence [S, R] into bf16 hi/lo (vectorized pair writes)
// ---------------------------------------------------------------------------
__global__ __launch_bounds__(256)
void split_inc_kernel(const float* __restrict__ inc)
{
    size_t i = ((size_t)blockIdx.x * 256 + threadIdx.x) * 2;
    float2 v = *(const float2*)(inc + i);
    __nv_bfloat16 h0 = __float2bfloat16(v.x);
    __nv_bfloat16 h1 = __float2bfloat16(v.y);
    __nv_bfloat162 hp, lp;
    hp.x = h0; hp.y = h1;
    lp.x = __float2bfloat16(v.x - __bfloat162float(h0));
    lp.y = __float2bfloat16(v.y - __bfloat162float(h1));
    *(__nv_bfloat162*)(g_ihi + i) = hp;
    *(__nv_bfloat162*)(g_ilo + i) = lp;
}

// ---------------------------------------------------------------------------
// Kernel 1: flux -> bf16 hi/lo split, r-pair per thread (bf16x2 stores)
// ---------------------------------------------------------------------------
__global__ __launch_bounds__(256)
void flux_kernel(const float* __restrict__ abundances,
                 const float* __restrict__ cr_rate,
                 const float* __restrict__ fuv_rate,
                 const float* __restrict__ alpha,
                 const float* __restrict__ beta,
                 const float* __restrict__ gamma,
                 const int*   __restrict__ rm,
                 const int*   __restrict__ rtype)
{
    int r0 = (blockIdx.x * 256 + threadIdx.x) * 2;   // r pair
    int b0 = blockIdx.y * 16;

    float al0 = alpha[r0],     al1 = alpha[r0 + 1];
    float be0 = beta[r0],      be1 = beta[r0 + 1];
    float ga0 = gamma[r0],     ga1 = gamma[r0 + 1];
    int   rt0 = rtype[r0],     rt1 = rtype[r0 + 1];
    int4  mm  = *(const int4*)(rm + 2 * r0);
    float eg0 = g_expg[r0],    eg1 = g_expg[r0 + 1];

    #pragma unroll 4
    for (int bb = 0; bb < 16; ++bb) {
        int b = b0 + bb;
        float lT = g_logT[b];
        float iT = g_invT[b];
        float cr = cr_rate[b];
        float fv = fuv_rate[b];

        float k0, k1;
        if (rt0 == 0)      k0 = al0 * __expf(fmaf(be0, lT, -ga0 * iT));
        else if (rt0 == 1) k0 = al0 * cr;
        else               k0 = al0 * eg0 * fv;
        if (rt1 == 0)      k1 = al1 * __expf(fmaf(be1, lT, -ga1 * iT));
        else if (rt1 == 1) k1 = al1 * cr;
        else               k1 = al1 * eg1 * fv;

        const float* abrow = abundances + (size_t)b * S_DIM;
        float v0 = k0 * ((mm.x < S_DIM) ? abrow[mm.x] : 1.0f)
                      * ((mm.y < S_DIM) ? abrow[mm.y] : 1.0f);
        float v1 = k1 * ((mm.z < S_DIM) ? abrow[mm.z] : 1.0f)
                      * ((mm.w < S_DIM) ? abrow[mm.w] : 1.0f);

        __nv_bfloat16 h0 = __float2bfloat16(v0);
        __nv_bfloat16 h1 = __float2bfloat16(v1);
        __nv_bfloat162 hp, lp;
        hp.x = h0; hp.y = h1;
        lp.x = __float2bfloat16(v0 - __bfloat162float(h0));
        lp.y = __float2bfloat16(v1 - __bfloat162float(h1));
        size_t idx = (size_t)b * R_DIM + r0;
        *(__nv_bfloat162*)(g_fhi + idx) = hp;
        *(__nv_bfloat162*)(g_flo + idx) = lp;
    }
}

// ---------------------------------------------------------------------------
// Kernel 2: mma.sync bf16 GEMM, split-K=4.
// CTA tile 128x128, BK=32, 256 threads / 8 warps (4m x 2n), warp tile 32x64.
// Grid (2 s, 64 b, 4 kz) = 512 CTAs -> scheduler keeps ~2 CTAs on every SM.
// Per-ktile order: h0-LDSM, h0-MMAs, h1-LDSM, sync, prefetch, h1-MMAs
// (barrier gates only shared reads; h1 MMAs overlap the cp.async issue).
// ---------------------------------------------------------------------------
#define BK 32
#define ROW_BYTES 80
#define TILE_BYTES (128 * ROW_BYTES)        // 10240
#define STAGE_BYTES (4 * TILE_BYTES)        // 40960
#define NSTAGE 2
#define SMEM_BYTES (NSTAGE * STAGE_BYTES)   // 81920 per CTA
#define OFF_AHI 0
#define OFF_ALO TILE_BYTES
#define OFF_BHI (2 * TILE_BYTES)
#define OFF_BLO (3 * TILE_BYTES)
#define KTILES_PER_CTA (KCHUNK / BK)        // 64

__device__ __forceinline__ void prefetch_stage(uint32_t sb, int stoff,
                                               int bm, int bn, int k0, int tid)
{
    #pragma unroll
    for (int i = 0; i < 2; ++i) {
        int idx = i * 256 + tid;            // 0..511
        int row = idx >> 2;                 // 0..127
        int c   = idx & 3;                  // 16B chunk in 64B row
        uint32_t so = (uint32_t)(stoff + row * ROW_BYTES + c * 16);
        size_t ga = (size_t)(bm + row) * R_DIM + k0 + c * 8;
        size_t gb = (size_t)(bn + row) * R_DIM + k0 + c * 8;
        CP16(sb + so + OFF_AHI, g_fhi + ga);
        CP16(sb + so + OFF_ALO, g_flo + ga);
        CP16(sb + so + OFF_BHI, g_ihi + gb);
        CP16(sb + so + OFF_BLO, g_ilo + gb);
    }
}

__global__ __launch_bounds__(256, 2)
void gemm_kernel()
{
    extern __shared__ char smbuf[];
    const uint32_t sb = s2u(smbuf);
    const int tid  = threadIdx.x;
    const int wid  = tid >> 5;
    const int lane = tid & 31;

    const int bn = blockIdx.x * 128;        // s tile
    const int bm = blockIdx.y * 128;        // b tile
    const int kz = blockIdx.z;              // k split index
    const int kbase = kz * KCHUNK;
    const int wm = (wid >> 1) * 32;         // warp m offset
    const int wn = (wid & 1) * 64;          // warp n offset

    float acc[2][8][4];
    #pragma unroll
    for (int i = 0; i < 2; ++i)
        #pragma unroll
        for (int j = 0; j < 8; ++j)
            #pragma unroll
            for (int q = 0; q < 4; ++q)
                acc[i][j][q] = 0.0f;

    prefetch_stage(sb, 0 * STAGE_BYTES, bm, bn, kbase + 0 * BK, tid);
    CP_COMMIT();
    prefetch_stage(sb, 1 * STAGE_BYTES, bm, bn, kbase + 1 * BK, tid);
    CP_COMMIT();

    const int a_row  = (lane & 15);
    const int a_koff = (lane >> 4) << 3;
    const int b_row  = (lane & 7) + ((lane >> 4) << 3);
    const int b_koff = (lane & 8);

    for (int t = 0; t < KTILES_PER_CTA; ++t) {
        CP_WAIT1();
        __syncthreads();
        const int stoff = (t & 1) * STAGE_BYTES;

        // ---- half 0: load fragments, run 48 MMAs ----
        uint32_t ah[2][4], al[2][4];
        uint32_t bh[4][4], bl[4][4];
        #pragma unroll
        for (int i = 0; i < 2; ++i) {
            uint32_t ar = sb + stoff +
                (uint32_t)((wm + i * 16 + a_row) * ROW_BYTES + a_koff * 2);
            LDSM4(ah[i], ar + OFF_AHI);
            LDSM4(al[i], ar + OFF_ALO);
        }
        #pragma unroll
        for (int j = 0; j < 4; ++j) {
            uint32_t br = sb + stoff +
                (uint32_t)((wn + j * 16 + b_row) * ROW_BYTES + b_koff * 2);
            LDSM4(bh[j], br + OFF_BHI);
            LDSM4(bl[j], br + OFF_BLO);
        }
        #pragma unroll
        for (int j = 0; j < 4; ++j)
            #pragma unroll
            for (int i = 0; i < 2; ++i) {
                MMA16816(acc[i][2 * j],     ah[i], bh[j][0], bh[j][1]);
                MMA16816(acc[i][2 * j + 1], ah[i], bh[j][2], bh[j][3]);
            }
        #pragma unroll
        for (int j = 0; j < 4; ++j)
            #pragma unroll
            for (int i = 0; i < 2; ++i) {
                MMA16816(acc[i][2 * j],     ah[i], bl[j][0], bl[j][1]);
                MMA16816(acc[i][2 * j + 1], ah[i], bl[j][2], bl[j][3]);
            }
        #pragma unroll
        for (int j = 0; j < 4; ++j)
            #pragma unroll
            for (int i = 0; i < 2; ++i) {
                MMA16816(acc[i][2 * j],     al[i], bh[j][0], bh[j][1]);
                MMA16816(acc[i][2 * j + 1], al[i], bh[j][2], bh[j][3]);
            }

        // ---- half 1: load fragments (last shared reads of this stage) ----
        #pragma unroll
        for (int i = 0; i < 2; ++i) {
            uint32_t ar = sb + stoff +
                (uint32_t)((wm + i * 16 + a_row) * ROW_BYTES + (16 + a_koff) * 2);
            LDSM4(ah[i], ar + OFF_AHI);
            LDSM4(al[i], ar + OFF_ALO);
        }
        #pragma unroll
        for (int j = 0; j < 4; ++j) {
            uint32_t br = sb + stoff +
                (uint32_t)((wn + j * 16 + b_row) * ROW_BYTES + (16 + b_koff) * 2);
            LDSM4(bh[j], br + OFF_BHI);
            LDSM4(bl[j], br + OFF_BLO);
        }

        // Stage fully consumed -> start refilling it while h1 MMAs run.
        __syncthreads();
        if (t + NSTAGE < KTILES_PER_CTA) {
            prefetch_stage(sb, (t & 1) * STAGE_BYTES, bm, bn,
                           kbase + (t + NSTAGE) * BK, tid);
        }
        CP_COMMIT();

        // ---- half 1: 48 MMAs overlap the cp.async issue/flight ----
        #pragma unroll
        for (int j = 0; j < 4; ++j)
            #pragma unroll
            for (int i = 0; i < 2; ++i) {
                MMA16816(acc[i][2 * j],     ah[i], bh[j][0], bh[j][1]);
                MMA16816(acc[i][2 * j + 1], ah[i], bh[j][2], bh[j][3]);
            }
        #pragma unroll
        for (int j = 0; j < 4; ++j)
            #pragma unroll
            for (int i = 0; i < 2; ++i) {
                MMA16816(acc[i][2 * j],     ah[i], bl[j][0], bl[j][1]);
                MMA16816(acc[i][2 * j + 1], ah[i], bl[j][2], bl[j][3]);
            }
        #pragma unroll
        for (int j = 0; j < 4; ++j)
            #pragma unroll
            for (int i = 0; i < 2; ++i) {
                MMA16816(acc[i][2 * j],     al[i], bh[j][0], bh[j][1]);
                MMA16816(acc[i][2 * j + 1], al[i], bh[j][2], bh[j][3]);
            }
    }

    // Epilogue -> partial buffer
    float* part = g_part[kz];
    const int eg = lane >> 2;
    const int ec = (lane & 3) * 2;
    #pragma unroll
    for (int i = 0; i < 2; ++i) {
        #pragma unroll
        for (int j = 0; j < 8; ++j) {
            int row = bm + wm + i * 16 + eg;
            int col = bn + wn + j * 8 + ec;
            float* p = part + (size_t)row * S_DIM + col;
            *(float2*)p = make_float2(acc[i][j][0], acc[i][j][1]);
            *(float2*)(p + 8 * S_DIM) = make_float2(acc[i][j][2], acc[i][j][3]);
        }
    }
}

// ---------------------------------------------------------------------------
// Kernel 3: reduce partials -> out
// ---------------------------------------------------------------------------
__global__ __launch_bounds__(256)
void reduce_kernel(float* __restrict__ out)
{
    size_t i = ((size_t)blockIdx.x * 256 + threadIdx.x) * 4;
    float4 a = *(const float4*)(g_part[0] + i);
    float4 b = *(const float4*)(g_part[1] + i);
    float4 c = *(const float4*)(g_part[2] + i);
    float4 d = *(const float4*)(g_part[3] + i);
    float4 v = make_float4((a.x + b.x) + (c.x + d.x),
                           (a.y + b.y) + (c.y + d.y),
                           (a.z + b.z) + (c.z + d.z),
                           (a.w + b.w) + (c.w + d.w));
    *(float4*)(out + i) = v;
}

// ---------------------------------------------------------------------------
// Input order: 0 time, 1 abundances, 2 temperature, 3 cr_rate, 4 fuv_rate,
// 5 incidence, 6 alpha, 7 beta, 8 gamma, 9 reactant_multipliers, 10 rtype
// ---------------------------------------------------------------------------
extern "C" void kernel_launch(void* const* d_in, const int* in_sizes, int n_in,
                              void* d_out, int out_size)
{
    const float* abundances  = (const float*)d_in[1];
    const float* temperature = (const float*)d_in[2];
    const float* cr_rate     = (const float*)d_in[3];
    const float* fuv_rate    = (const float*)d_in[4];
    const float* incidence   = (const float*)d_in[5];
    const float* alpha       = (const float*)d_in[6];
    const float* beta        = (const float*)d_in[7];
    const float* gamma       = (const float*)d_in[8];
    const int*   rm          = (const int*)d_in[9];
    const int*   rtype       = (const int*)d_in[10];
    float*       out         = (float*)d_out;

    cudaFuncSetAttribute(gemm_kernel,
                         cudaFuncAttributeMaxDynamicSharedMemorySize, SMEM_BYTES);

    precompute_kernel<<<(B_DIM + 255) / 256, 256>>>(temperature, gamma);

    split_inc_kernel<<<(S_DIM * R_DIM) / 512, 256>>>(incidence);

    flux_kernel<<<dim3(R_DIM / 512, B_DIM / 16), 256>>>(
        abundances, cr_rate, fuv_rate, alpha, beta, gamma, rm, rtype);

    gemm_kernel<<<dim3(S_DIM / 128, B_DIM / 128, KSPLIT), 256, SMEM_BYTES>>>();

    reduce_kernel<<<(B_DIM * S_DIM) / 1024, 256>>>(out);
}

// round 12
// speedup vs baseline: 1.3379x; 1.3379x over previous
#include <cuda_runtime.h>
#include <cuda_bf16.h>
#include <cstdint>

#define B_DIM 8192
#define S_DIM 256
#define R_DIM 8192
#define KSPLIT 2
#define KCHUNK (R_DIM / KSPLIT)             // 4096
#define AB_STRIDE 257                        // padded abundance row (col 256 = 1.0)

// ---------------------------------------------------------------------------
// Device-global scratch
// ---------------------------------------------------------------------------
__device__ __nv_bfloat16 g_fhi[(size_t)B_DIM * R_DIM];  // 128 MB
__device__ __nv_bfloat16 g_flo[(size_t)B_DIM * R_DIM];  // 128 MB
__device__ __nv_bfloat16 g_ihi[(size_t)S_DIM * R_DIM];  // 4 MB
__device__ __nv_bfloat16 g_ilo[(size_t)S_DIM * R_DIM];  // 4 MB
__device__ float g_part[KSPLIT][(size_t)B_DIM * S_DIM]; // 16 MB partials
__device__ float g_abpad[(size_t)B_DIM * AB_STRIDE];    // 8.4 MB padded abundances
__device__ float g_logT[B_DIM];
__device__ float g_invT[B_DIM];
__device__ float g_expg[R_DIM];

// ---------------------------------------------------------------------------
// PTX helpers (compute_103-portable: mma.sync / ldmatrix / cp.async)
// ---------------------------------------------------------------------------
__device__ __forceinline__ uint32_t s2u(const void* p) {
    uint32_t a;
    asm("{ .reg .u64 t; cvta.to.shared.u64 t, %1; cvt.u32.u64 %0, t; }"
        : "=r"(a) : "l"(p));
    return a;
}

#define LDSM4(r, addr)                                                         \
    asm volatile("ldmatrix.sync.aligned.m8n8.x4.shared.b16 {%0,%1,%2,%3}, [%4];" \
                 : "=r"((r)[0]), "=r"((r)[1]), "=r"((r)[2]), "=r"((r)[3])      \
                 : "r"(addr))

#define MMA16816(c, a, b0, b1)                                                 \
    asm volatile("mma.sync.aligned.m16n8k16.row.col.f32.bf16.bf16.f32 "        \
                 "{%0,%1,%2,%3}, {%4,%5,%6,%7}, {%8,%9}, {%0,%1,%2,%3};"       \
                 : "+f"((c)[0]), "+f"((c)[1]), "+f"((c)[2]), "+f"((c)[3])      \
                 : "r"((a)[0]), "r"((a)[1]), "r"((a)[2]), "r"((a)[3]),         \
                   "r"(b0), "r"(b1))

#define CP16CG(saddr, gptr)                                                    \
    asm volatile("cp.async.cg.shared.global [%0], [%1], 16;"                   \
                 :: "r"(saddr), "l"(gptr))
#define CP16CA(saddr, gptr)                                                    \
    asm volatile("cp.async.ca.shared.global [%0], [%1], 16;"                   \
                 :: "r"(saddr), "l"(gptr))

#define CP_COMMIT() asm volatile("cp.async.commit_group;" ::: "memory")
#define CP_WAIT1()  asm volatile("cp.async.wait_group 1;" ::: "memory")

// ---------------------------------------------------------------------------
// Kernel 0: per-b and per-r precomputation
// ---------------------------------------------------------------------------
__global__ void precompute_kernel(const float* __restrict__ temperature,
                                  const float* __restrict__ gamma)
{
    int i = blockIdx.x * blockDim.x + threadIdx.x;
    if (i < B_DIM) {
        float T = temperature[i];
        g_logT[i] = logf(T * (1.0f / 300.0f));
        g_invT[i] = 1.0f / T;
    }
    if (i < R_DIM) {
        g_expg[i] = expf(-gamma[i]);
    }
}

// ---------------------------------------------------------------------------
// Kernel 0a: build padded abundance array (col 256 = 1.0) for branch-free
// gathers in the flux kernel.
// ---------------------------------------------------------------------------
__global__ __launch_bounds__(256)
void pad_ab_kernel(const float* __restrict__ abundances)
{
    int b = blockIdx.x;
    int t = threadIdx.x;
    g_abpad[(size_t)b * AB_STRIDE + t] = abundances[(size_t)b * S_DIM + t];
    if (t == 0) g_abpad[(size_t)b * AB_STRIDE + S_DIM] = 1.0f;
}

// ---------------------------------------------------------------------------
// Kernel 0b: split incidence [S, R] into bf16 hi/lo (vectorized pair writes)
// ---------------------------------------------------------------------------
__global__ __launch_bounds__(256)
void split_inc_kernel(const float* __restrict__ inc)
{
    size_t i = ((size_t)blockIdx.x * 256 + threadIdx.x) * 2;
    float2 v = *(const float2*)(inc + i);
    __nv_bfloat16 h0 = __float2bfloat16(v.x);
    __nv_bfloat16 h1 = __float2bfloat16(v.y);
    __nv_bfloat162 hp, lp;
    hp.x = h0; hp.y = h1;
    lp.x = __float2bfloat16(v.x - __bfloat162float(h0));
    lp.y = __float2bfloat16(v.y - __bfloat162float(h1));
    *(__nv_bfloat162*)(g_ihi + i) = hp;
    *(__nv_bfloat162*)(g_ilo + i) = lp;
}

// ---------------------------------------------------------------------------
// Kernel 1: flux -> bf16 hi/lo split, r-pair per thread (bf16x2 stores).
// Branch-free gathers from the padded abundance array.
// ---------------------------------------------------------------------------
__global__ __launch_bounds__(256)
void flux_kernel(const float* __restrict__ cr_rate,
                 const float* __restrict__ fuv_rate,
                 const float* __restrict__ alpha,
                 const float* __restrict__ beta,
                 const float* __restrict__ gamma,
                 const int*   __restrict__ rm,
                 const int*   __restrict__ rtype)
{
    int r0 = (blockIdx.x * 256 + threadIdx.x) * 2;   // r pair
    int b0 = blockIdx.y * 16;

    float al0 = alpha[r0],     al1 = alpha[r0 + 1];
    float be0 = beta[r0],      be1 = beta[r0 + 1];
    float ga0 = gamma[r0],     ga1 = gamma[r0 + 1];
    int   rt0 = rtype[r0],     rt1 = rtype[r0 + 1];
    int4  mm  = *(const int4*)(rm + 2 * r0);
    float eg0 = g_expg[r0],    eg1 = g_expg[r0 + 1];

    #pragma unroll 4
    for (int bb = 0; bb < 16; ++bb) {
        int b = b0 + bb;
        float lT = g_logT[b];
        float iT = g_invT[b];
        float cr = cr_rate[b];
        float fv = fuv_rate[b];

        float k0, k1;
        if (rt0 == 0)      k0 = al0 * __expf(fmaf(be0, lT, -ga0 * iT));
        else if (rt0 == 1) k0 = al0 * cr;
        else               k0 = al0 * eg0 * fv;
        if (rt1 == 0)      k1 = al1 * __expf(fmaf(be1, lT, -ga1 * iT));
        else if (rt1 == 1) k1 = al1 * cr;
        else               k1 = al1 * eg1 * fv;

        const float* abrow = g_abpad + (size_t)b * AB_STRIDE;
        float v0 = k0 * abrow[mm.x] * abrow[mm.y];
        float v1 = k1 * abrow[mm.z] * abrow[mm.w];

        __nv_bfloat16 h0 = __float2bfloat16(v0);
        __nv_bfloat16 h1 = __float2bfloat16(v1);
        __nv_bfloat162 hp, lp;
        hp.x = h0; hp.y = h1;
        lp.x = __float2bfloat16(v0 - __bfloat162float(h0));
        lp.y = __float2bfloat16(v1 - __bfloat162float(h1));
        size_t idx = (size_t)b * R_DIM + r0;
        *(__nv_bfloat162*)(g_fhi + idx) = hp;
        *(__nv_bfloat162*)(g_flo + idx) = lp;
    }
}

// ---------------------------------------------------------------------------
// Kernel 2: mma.sync bf16 GEMM, split-K=2 (the proven R10 structure).
// CTA tile 128x128, BK=32, 256 threads / 8 warps (4m x 2n), warp tile 32x64.
// A tiles streamed with cp.async.cg; B tiles cached with cp.async.ca.
// ---------------------------------------------------------------------------
#define BK 32
#define ROW_BYTES 80
#define TILE_BYTES (128 * ROW_BYTES)        // 10240
#define STAGE_BYTES (4 * TILE_BYTES)        // 40960
#define NSTAGE 2
#define SMEM_BYTES (NSTAGE * STAGE_BYTES)   // 81920 per CTA
#define OFF_AHI 0
#define OFF_ALO TILE_BYTES
#define OFF_BHI (2 * TILE_BYTES)
#define OFF_BLO (3 * TILE_BYTES)
#define KTILES_PER_CTA (KCHUNK / BK)        // 128

__device__ __forceinline__ void prefetch_stage(uint32_t sb, int stoff,
                                               int bm, int bn, int k0, int tid)
{
    #pragma unroll
    for (int i = 0; i < 2; ++i) {
        int idx = i * 256 + tid;            // 0..511
        int row = idx >> 2;                 // 0..127
        int c   = idx & 3;                  // 16B chunk in 64B row
        uint32_t so = (uint32_t)(stoff + row * ROW_BYTES + c * 16);
        size_t ga = (size_t)(bm + row) * R_DIM + k0 + c * 8;
        size_t gb = (size_t)(bn + row) * R_DIM + k0 + c * 8;
        CP16CG(sb + so + OFF_AHI, g_fhi + ga);
        CP16CG(sb + so + OFF_ALO, g_flo + ga);
        CP16CA(sb + so + OFF_BHI, g_ihi + gb);
        CP16CA(sb + so + OFF_BLO, g_ilo + gb);
    }
}

__global__ __launch_bounds__(256, 2)
void gemm_kernel()
{
    extern __shared__ char smbuf[];
    const uint32_t sb = s2u(smbuf);
    const int tid  = threadIdx.x;
    const int wid  = tid >> 5;
    const int lane = tid & 31;

    const int bn = blockIdx.x * 128;        // s tile
    const int bm = blockIdx.y * 128;        // b tile
    const int kz = blockIdx.z;              // k split index
    const int kbase = kz * KCHUNK;
    const int wm = (wid >> 1) * 32;         // warp m offset
    const int wn = (wid & 1) * 64;          // warp n offset

    float acc[2][8][4];
    #pragma unroll
    for (int i = 0; i < 2; ++i)
        #pragma unroll
        for (int j = 0; j < 8; ++j)
            #pragma unroll
            for (int q = 0; q < 4; ++q)
                acc[i][j][q] = 0.0f;

    prefetch_stage(sb, 0 * STAGE_BYTES, bm, bn, kbase + 0 * BK, tid);
    CP_COMMIT();
    prefetch_stage(sb, 1 * STAGE_BYTES, bm, bn, kbase + 1 * BK, tid);
    CP_COMMIT();

    const int a_row  = (lane & 15);
    const int a_koff = (lane >> 4) << 3;
    const int b_row  = (lane & 7) + ((lane >> 4) << 3);
    const int b_koff = (lane & 8);

    for (int t = 0; t < KTILES_PER_CTA; ++t) {
        CP_WAIT1();
        __syncthreads();
        const int stoff = (t & 1) * STAGE_BYTES;

        #pragma unroll
        for (int h = 0; h < 2; ++h) {       // k16 halves of the BK=32 tile
            uint32_t ah[2][4], al[2][4];
            #pragma unroll
            for (int i = 0; i < 2; ++i) {
                uint32_t ar = sb + stoff +
                    (uint32_t)((wm + i * 16 + a_row) * ROW_BYTES + (h * 16 + a_koff) * 2);
                LDSM4(ah[i], ar + OFF_AHI);
                LDSM4(al[i], ar + OFF_ALO);
            }
            uint32_t bh[4][4], bl[4][4];
            #pragma unroll
            for (int j = 0; j < 4; ++j) {
                uint32_t br = sb + stoff +
                    (uint32_t)((wn + j * 16 + b_row) * ROW_BYTES + (h * 16 + b_koff) * 2);
                LDSM4(bh[j], br + OFF_BHI);
                LDSM4(bl[j], br + OFF_BLO);
            }

            #pragma unroll
            for (int j = 0; j < 4; ++j)
                #pragma unroll
                for (int i = 0; i < 2; ++i) {
                    MMA16816(acc[i][2 * j],     ah[i], bh[j][0], bh[j][1]);
                    MMA16816(acc[i][2 * j + 1], ah[i], bh[j][2], bh[j][3]);
                }
            #pragma unroll
            for (int j = 0; j < 4; ++j)
                #pragma unroll
                for (int i = 0; i < 2; ++i) {
                    MMA16816(acc[i][2 * j],     ah[i], bl[j][0], bl[j][1]);
                    MMA16816(acc[i][2 * j + 1], ah[i], bl[j][2], bl[j][3]);
                }
            #pragma unroll
            for (int j = 0; j < 4; ++j)
                #pragma unroll
                for (int i = 0; i < 2; ++i) {
                    MMA16816(acc[i][2 * j],     al[i], bh[j][0], bh[j][1]);
                    MMA16816(acc[i][2 * j + 1], al[i], bh[j][2], bh[j][3]);
                }
        }

        __syncthreads();
        if (t + NSTAGE < KTILES_PER_CTA) {
            prefetch_stage(sb, (t & 1) * STAGE_BYTES, bm, bn,
                           kbase + (t + NSTAGE) * BK, tid);
        }
        CP_COMMIT();
    }

    // Epilogue -> partial buffer
    float* part = g_part[kz];
    const int eg = lane >> 2;
    const int ec = (lane & 3) * 2;
    #pragma unroll
    for (int i = 0; i < 2; ++i) {
        #pragma unroll
        for (int j = 0; j < 8; ++j) {
            int row = bm + wm + i * 16 + eg;
            int col = bn + wn + j * 8 + ec;
            float* p = part + (size_t)row * S_DIM + col;
            *(float2*)p = make_float2(acc[i][j][0], acc[i][j][1]);
            *(float2*)(p + 8 * S_DIM) = make_float2(acc[i][j][2], acc[i][j][3]);
        }
    }
}

// ---------------------------------------------------------------------------
// Kernel 3: reduce partials -> out
// ---------------------------------------------------------------------------
__global__ __launch_bounds__(256)
void reduce_kernel(float* __restrict__ out)
{
    size_t i = ((size_t)blockIdx.x * 256 + threadIdx.x) * 4;
    float4 a = *(const float4*)(g_part[0] + i);
    float4 b = *(const float4*)(g_part[1] + i);
    float4 v = make_float4(a.x + b.x, a.y + b.y, a.z + b.z, a.w + b.w);
    *(float4*)(out + i) = v;
}

// ---------------------------------------------------------------------------
// Input order: 0 time, 1 abundances, 2 temperature, 3 cr_rate, 4 fuv_rate,
// 5 incidence, 6 alpha, 7 beta, 8 gamma, 9 reactant_multipliers, 10 rtype
// ---------------------------------------------------------------------------
extern "C" void kernel_launch(void* const* d_in, const int* in_sizes, int n_in,
                              void* d_out, int out_size)
{
    const float* abundances  = (const float*)d_in[1];
    const float* temperature = (const float*)d_in[2];
    const float* cr_rate     = (const float*)d_in[3];
    const float* fuv_rate    = (const float*)d_in[4];
    const float* incidence   = (const float*)d_in[5];
    const float* alpha       = (const float*)d_in[6];
    const float* beta        = (const float*)d_in[7];
    const float* gamma       = (const float*)d_in[8];
    const int*   rm          = (const int*)d_in[9];
    const int*   rtype       = (const int*)d_in[10];
    float*       out         = (float*)d_out;

    cudaFuncSetAttribute(gemm_kernel,
                         cudaFuncAttributeMaxDynamicSharedMemorySize, SMEM_BYTES);

    precompute_kernel<<<(B_DIM + 255) / 256, 256>>>(temperature, gamma);

    pad_ab_kernel<<<B_DIM, 256>>>(abundances);

    split_inc_kernel<<<(S_DIM * R_DIM) / 512, 256>>>(incidence);

    flux_kernel<<<dim3(R_DIM / 512, B_DIM / 16), 256>>>(
        cr_rate, fuv_rate, alpha, beta, gamma, rm, rtype);

    gemm_kernel<<<dim3(S_DIM / 128, B_DIM / 128, KSPLIT), 256, SMEM_BYTES>>>();

    reduce_kernel<<<(B_DIM * S_DIM) / 1024, 256>>>(out);
}

// round 13
// speedup vs baseline: 1.5210x; 1.1368x over previous
#include <cuda_runtime.h>
#include <cuda_bf16.h>
#include <cstdint>

#define B_DIM 8192
#define S_DIM 256
#define R_DIM 8192
#define KSPLIT 2
#define KCHUNK (R_DIM / KSPLIT)             // 4096

// ---------------------------------------------------------------------------
// Device-global scratch
// ---------------------------------------------------------------------------
__device__ __nv_bfloat16 g_fhi[(size_t)B_DIM * R_DIM];  // 128 MB
__device__ __nv_bfloat16 g_flo[(size_t)B_DIM * R_DIM];  // 128 MB
__device__ __nv_bfloat16 g_ihi[(size_t)S_DIM * R_DIM];  // 4 MB
__device__ __nv_bfloat16 g_ilo[(size_t)S_DIM * R_DIM];  // 4 MB
__device__ float g_part[KSPLIT][(size_t)B_DIM * S_DIM]; // 16 MB partials
__device__ float g_logT[B_DIM];
__device__ float g_invT[B_DIM];
__device__ float g_expg[R_DIM];

// ---------------------------------------------------------------------------
// PTX helpers (compute_103-portable: mma.sync / ldmatrix / cp.async)
// ---------------------------------------------------------------------------
__device__ __forceinline__ uint32_t s2u(const void* p) {
    uint32_t a;
    asm("{ .reg .u64 t; cvta.to.shared.u64 t, %1; cvt.u32.u64 %0, t; }"
        : "=r"(a) : "l"(p));
    return a;
}

#define LDSM4(r, addr)                                                         \
    asm volatile("ldmatrix.sync.aligned.m8n8.x4.shared.b16 {%0,%1,%2,%3}, [%4];" \
                 : "=r"((r)[0]), "=r"((r)[1]), "=r"((r)[2]), "=r"((r)[3])      \
                 : "r"(addr))

#define MMA16816(c, a, b0, b1)                                                 \
    asm volatile("mma.sync.aligned.m16n8k16.row.col.f32.bf16.bf16.f32 "        \
                 "{%0,%1,%2,%3}, {%4,%5,%6,%7}, {%8,%9}, {%0,%1,%2,%3};"       \
                 : "+f"((c)[0]), "+f"((c)[1]), "+f"((c)[2]), "+f"((c)[3])      \
                 : "r"((a)[0]), "r"((a)[1]), "r"((a)[2]), "r"((a)[3]),         \
                   "r"(b0), "r"(b1))

#define CP16(saddr, gptr)                                                      \
    asm volatile("cp.async.cg.shared.global [%0], [%1], 16;"                   \
                 :: "r"(saddr), "l"(gptr))

#define CP_COMMIT() asm volatile("cp.async.commit_group;" ::: "memory")
#define CP_WAIT1()  asm volatile("cp.async.wait_group 1;" ::: "memory")

// ---------------------------------------------------------------------------
// Kernel 0: per-b and per-r precomputation
// ---------------------------------------------------------------------------
__global__ void precompute_kernel(const float* __restrict__ temperature,
                                  const float* __restrict__ gamma)
{
    int i = blockIdx.x * blockDim.x + threadIdx.x;
    if (i < B_DIM) {
        float T = temperature[i];
        g_logT[i] = logf(T * (1.0f / 300.0f));
        g_invT[i] = 1.0f / T;
    }
    if (i < R_DIM) {
        g_expg[i] = expf(-gamma[i]);
    }
}

// ---------------------------------------------------------------------------
// Kernel 0b: split incidence [S, R] into bf16 hi/lo (vectorized pair writes)
// ---------------------------------------------------------------------------
__global__ __launch_bounds__(256)
void split_inc_kernel(const float* __restrict__ inc)
{
    size_t i = ((size_t)blockIdx.x * 256 + threadIdx.x) * 2;
    float2 v = *(const float2*)(inc + i);
    __nv_bfloat16 h0 = __float2bfloat16(v.x);
    __nv_bfloat16 h1 = __float2bfloat16(v.y);
    __nv_bfloat162 hp, lp;
    hp.x = h0; hp.y = h1;
    lp.x = __float2bfloat16(v.x - __bfloat162float(h0));
    lp.y = __float2bfloat16(v.y - __bfloat162float(h1));
    *(__nv_bfloat162*)(g_ihi + i) = hp;
    *(__nv_bfloat162*)(g_ilo + i) = lp;
}

// ---------------------------------------------------------------------------
// Kernel 1: flux -> bf16 hi/lo split. Block = 512 r's x 16 b's. The 16
// abundance rows are staged in smem (coalesced, aligned global reads);
// gathers become LDS hits instead of L1tex wavefront storms.
// ---------------------------------------------------------------------------
__global__ __launch_bounds__(256)
void flux_kernel(const float* __restrict__ abundances,
                 const float* __restrict__ cr_rate,
                 const float* __restrict__ fuv_rate,
                 const float* __restrict__ alpha,
                 const float* __restrict__ beta,
                 const float* __restrict__ gamma,
                 const int*   __restrict__ rm,
                 const int*   __restrict__ rtype)
{
    __shared__ float s_ab[16][257];          // col 256 = 1.0 (pad species)

    const int tid = threadIdx.x;
    int r0 = (blockIdx.x * 256 + tid) * 2;   // r pair
    int b0 = blockIdx.y * 16;

    // Stage 16 abundance rows (aligned 128B global reads).
    #pragma unroll
    for (int i = 0; i < 16; ++i) {
        int idx = i * 256 + tid;             // 0..4095
        int row = idx >> 8;
        int col = idx & 255;
        s_ab[row][col] = abundances[(size_t)(b0 + row) * S_DIM + col];
    }
    if (tid < 16) s_ab[tid][256] = 1.0f;
    __syncthreads();

    float al0 = alpha[r0],     al1 = alpha[r0 + 1];
    float be0 = beta[r0],      be1 = beta[r0 + 1];
    float ga0 = gamma[r0],     ga1 = gamma[r0 + 1];
    int   rt0 = rtype[r0],     rt1 = rtype[r0 + 1];
    int4  mm  = *(const int4*)(rm + 2 * r0);
    float eg0 = g_expg[r0],    eg1 = g_expg[r0 + 1];

    #pragma unroll 4
    for (int bb = 0; bb < 16; ++bb) {
        int b = b0 + bb;
        float lT = g_logT[b];
        float iT = g_invT[b];
        float cr = cr_rate[b];
        float fv = fuv_rate[b];

        float k0, k1;
        if (rt0 == 0)      k0 = al0 * __expf(fmaf(be0, lT, -ga0 * iT));
        else if (rt0 == 1) k0 = al0 * cr;
        else               k0 = al0 * eg0 * fv;
        if (rt1 == 0)      k1 = al1 * __expf(fmaf(be1, lT, -ga1 * iT));
        else if (rt1 == 1) k1 = al1 * cr;
        else               k1 = al1 * eg1 * fv;

        const float* abrow = s_ab[bb];
        float v0 = k0 * abrow[mm.x] * abrow[mm.y];
        float v1 = k1 * abrow[mm.z] * abrow[mm.w];

        __nv_bfloat16 h0 = __float2bfloat16(v0);
        __nv_bfloat16 h1 = __float2bfloat16(v1);
        __nv_bfloat162 hp, lp;
        hp.x = h0; hp.y = h1;
        lp.x = __float2bfloat16(v0 - __bfloat162float(h0));
        lp.y = __float2bfloat16(v1 - __bfloat162float(h1));
        size_t idx = (size_t)b * R_DIM + r0;
        *(__nv_bfloat162*)(g_fhi + idx) = hp;
        *(__nv_bfloat162*)(g_flo + idx) = lp;
    }
}

// ---------------------------------------------------------------------------
// Kernel 2: mma.sync bf16 GEMM, split-K=2 (exact R10 structure, all .cg).
// CTA tile 128x128, BK=32, 256 threads / 8 warps (4m x 2n), warp tile 32x64.
// ---------------------------------------------------------------------------
#define BK 32
#define ROW_BYTES 80
#define TILE_BYTES (128 * ROW_BYTES)        // 10240
#define STAGE_BYTES (4 * TILE_BYTES)        // 40960
#define NSTAGE 2
#define SMEM_BYTES (NSTAGE * STAGE_BYTES)   // 81920 per CTA
#define OFF_AHI 0
#define OFF_ALO TILE_BYTES
#define OFF_BHI (2 * TILE_BYTES)
#define OFF_BLO (3 * TILE_BYTES)
#define KTILES_PER_CTA (KCHUNK / BK)        // 128

__device__ __forceinline__ void prefetch_stage(uint32_t sb, int stoff,
                                               int bm, int bn, int k0, int tid)
{
    #pragma unroll
    for (int i = 0; i < 2; ++i) {
        int idx = i * 256 + tid;            // 0..511
        int row = idx >> 2;                 // 0..127
        int c   = idx & 3;                  // 16B chunk in 64B row
        uint32_t so = (uint32_t)(stoff + row * ROW_BYTES + c * 16);
        size_t ga = (size_t)(bm + row) * R_DIM + k0 + c * 8;
        size_t gb = (size_t)(bn + row) * R_DIM + k0 + c * 8;
        CP16(sb + so + OFF_AHI, g_fhi + ga);
        CP16(sb + so + OFF_ALO, g_flo + ga);
        CP16(sb + so + OFF_BHI, g_ihi + gb);
        CP16(sb + so + OFF_BLO, g_ilo + gb);
    }
}

__global__ __launch_bounds__(256, 2)
void gemm_kernel()
{
    extern __shared__ char smbuf[];
    const uint32_t sb = s2u(smbuf);
    const int tid  = threadIdx.x;
    const int wid  = tid >> 5;
    const int lane = tid & 31;

    const int bn = blockIdx.x * 128;        // s tile
    const int bm = blockIdx.y * 128;        // b tile
    const int kz = blockIdx.z;              // k split index
    const int kbase = kz * KCHUNK;
    const int wm = (wid >> 1) * 32;         // warp m offset
    const int wn = (wid & 1) * 64;          // warp n offset

    float acc[2][8][4];
    #pragma unroll
    for (int i = 0; i < 2; ++i)
        #pragma unroll
        for (int j = 0; j < 8; ++j)
            #pragma unroll
            for (int q = 0; q < 4; ++q)
                acc[i][j][q] = 0.0f;

    prefetch_stage(sb, 0 * STAGE_BYTES, bm, bn, kbase + 0 * BK, tid);
    CP_COMMIT();
    prefetch_stage(sb, 1 * STAGE_BYTES, bm, bn, kbase + 1 * BK, tid);
    CP_COMMIT();

    const int a_row  = (lane & 15);
    const int a_koff = (lane >> 4) << 3;
    const int b_row  = (lane & 7) + ((lane >> 4) << 3);
    const int b_koff = (lane & 8);

    for (int t = 0; t < KTILES_PER_CTA; ++t) {
        CP_WAIT1();
        __syncthreads();
        const int stoff = (t & 1) * STAGE_BYTES;

        #pragma unroll
        for (int h = 0; h < 2; ++h) {       // k16 halves of the BK=32 tile
            uint32_t ah[2][4], al[2][4];
            #pragma unroll
            for (int i = 0; i < 2; ++i) {
                uint32_t ar = sb + stoff +
                    (uint32_t)((wm + i * 16 + a_row) * ROW_BYTES + (h * 16 + a_koff) * 2);
                LDSM4(ah[i], ar + OFF_AHI);
                LDSM4(al[i], ar + OFF_ALO);
            }
            uint32_t bh[4][4], bl[4][4];
            #pragma unroll
            for (int j = 0; j < 4; ++j) {
                uint32_t br = sb + stoff +
                    (uint32_t)((wn + j * 16 + b_row) * ROW_BYTES + (h * 16 + b_koff) * 2);
                LDSM4(bh[j], br + OFF_BHI);
                LDSM4(bl[j], br + OFF_BLO);
            }

            #pragma unroll
            for (int j = 0; j < 4; ++j)
                #pragma unroll
                for (int i = 0; i < 2; ++i) {
                    MMA16816(acc[i][2 * j],     ah[i], bh[j][0], bh[j][1]);
                    MMA16816(acc[i][2 * j + 1], ah[i], bh[j][2], bh[j][3]);
                }
            #pragma unroll
            for (int j = 0; j < 4; ++j)
                #pragma unroll
                for (int i = 0; i < 2; ++i) {
                    MMA16816(acc[i][2 * j],     ah[i], bl[j][0], bl[j][1]);
                    MMA16816(acc[i][2 * j + 1], ah[i], bl[j][2], bl[j][3]);
                }
            #pragma unroll
            for (int j = 0; j < 4; ++j)
                #pragma unroll
                for (int i = 0; i < 2; ++i) {
                    MMA16816(acc[i][2 * j],     al[i], bh[j][0], bh[j][1]);
                    MMA16816(acc[i][2 * j + 1], al[i], bh[j][2], bh[j][3]);
                }
        }

        __syncthreads();
        if (t + NSTAGE < KTILES_PER_CTA) {
            prefetch_stage(sb, (t & 1) * STAGE_BYTES, bm, bn,
                           kbase + (t + NSTAGE) * BK, tid);
        }
        CP_COMMIT();
    }

    // Epilogue -> partial buffer
    float* part = g_part[kz];
    const int eg = lane >> 2;
    const int ec = (lane & 3) * 2;
    #pragma unroll
    for (int i = 0; i < 2; ++i) {
        #pragma unroll
        for (int j = 0; j < 8; ++j) {
            int row = bm + wm + i * 16 + eg;
            int col = bn + wn + j * 8 + ec;
            float* p = part + (size_t)row * S_DIM + col;
            *(float2*)p = make_float2(acc[i][j][0], acc[i][j][1]);
            *(float2*)(p + 8 * S_DIM) = make_float2(acc[i][j][2], acc[i][j][3]);
        }
    }
}

// ---------------------------------------------------------------------------
// Kernel 3: reduce partials -> out
// ---------------------------------------------------------------------------
__global__ __launch_bounds__(256)
void reduce_kernel(float* __restrict__ out)
{
    size_t i = ((size_t)blockIdx.x * 256 + threadIdx.x) * 4;
    float4 a = *(const float4*)(g_part[0] + i);
    float4 b = *(const float4*)(g_part[1] + i);
    float4 v = make_float4(a.x + b.x, a.y + b.y, a.z + b.z, a.w + b.w);
    *(float4*)(out + i) = v;
}

// ---------------------------------------------------------------------------
// Input order: 0 time, 1 abundances, 2 temperature, 3 cr_rate, 4 fuv_rate,
// 5 incidence, 6 alpha, 7 beta, 8 gamma, 9 reactant_multipliers, 10 rtype
// ---------------------------------------------------------------------------
extern "C" void kernel_launch(void* const* d_in, const int* in_sizes, int n_in,
                              void* d_out, int out_size)
{
    const float* abundances  = (const float*)d_in[1];
    const float* temperature = (const float*)d_in[2];
    const float* cr_rate     = (const float*)d_in[3];
    const float* fuv_rate    = (const float*)d_in[4];
    const float* incidence   = (const float*)d_in[5];
    const float* alpha       = (const float*)d_in[6];
    const float* beta        = (const float*)d_in[7];
    const float* gamma       = (const float*)d_in[8];
    const int*   rm          = (const int*)d_in[9];
    const int*   rtype       = (const int*)d_in[10];
    float*       out         = (float*)d_out;

    cudaFuncSetAttribute(gemm_kernel,
                         cudaFuncAttributeMaxDynamicSharedMemorySize, SMEM_BYTES);

    precompute_kernel<<<(B_DIM + 255) / 256, 256>>>(temperature, gamma);

    split_inc_kernel<<<(S_DIM * R_DIM) / 512, 256>>>(incidence);

    flux_kernel<<<dim3(R_DIM / 512, B_DIM / 16), 256>>>(
        abundances, cr_rate, fuv_rate, alpha, beta, gamma, rm, rtype);

    gemm_kernel<<<dim3(S_DIM / 128, B_DIM / 128, KSPLIT), 256, SMEM_BYTES>>>();

    reduce_kernel<<<(B_DIM * S_DIM) / 1024, 256>>>(out);
}